// round 14
// baseline (speedup 1.0000x reference)
#include <cuda_runtime.h>
#include <math.h>
#include <stdint.h>

#define BATCH 8
#define ANUM 15
#define HH 100
#define WW 168
#define NPER (ANUM*HH*WW)      // 252000
#define N4 (NPER/4)            // 63000
#define PRE 2000
#define POST 1000
#define CAND_CAP 4096
#define NWORDS 32              // ceil(PRE/64)
#define ROWT 256               // rows per nms tile
#define STRIDEF 8.0f
#define HB1 64                 // blocks per image, hist kernels
#define HB2 64                 // blocks per image, compact

// ---------------- scratch (no allocations allowed) ----------------
__device__ unsigned int       g_hist0[BATCH][256];   // zeroed by k_reduce_out
__device__ unsigned int       g_hist1[BATCH][256];
__device__ unsigned int       g_pref[BATCH];
__device__ unsigned int       g_krem[BATCH];
__device__ unsigned long long g_cand[BATCH][CAND_CAP];
__device__ int                g_ccnt[BATCH];         // read+reset by tid0 of k_sort
__device__ float              g_tsc[BATCH][PRE];
__device__ int                g_ridx[BATCH][PRE];    // sorted anchor indices
__device__ float4             g_box[BATCH][PRE];     // (x1,y1,x2,y2) output
__device__ float4             g_boxn[BATCH][PRE];    // (-x1,-y1,x2,y2) for IoU
__device__ float              g_area[BATCH][PRE];    // exact reference-order area
__device__ float              g_a07[BATCH][PRE];     // 0.7f * area
__device__ unsigned int       g_valmask32[BATCH][64];
__device__ unsigned long long g_mask[BATCH][PRE][NWORDS];   // 4 MB

__device__ __forceinline__ void suffix_scan256(unsigned int* cnts, int t) {
    #pragma unroll
    for (int off = 1; off < 256; off <<= 1) {
        unsigned int add = (t + off < 256) ? cnts[t + off] : 0u;
        __syncthreads();
        cnts[t] += add;
        __syncthreads();
    }
}

// warp-aggregated histogram add: one atomic per distinct bin per warp step
__device__ __forceinline__ void hadd(unsigned int* sh, unsigned int bin) {
    unsigned int am = __activemask();
    unsigned int m = __match_any_sync(am, bin);
    int leader = __ffs(m) - 1;
    if ((int)(threadIdx.x & 31) == leader) atomicAdd(&sh[bin], __popc(m));
}

// bitonic compare-exchange via warp shuffle (stride j <= 16)
__device__ __forceinline__ unsigned long long bshfl(
    unsigned long long v, int i, int j, int k) {
    unsigned long long p = __shfl_xor_sync(0xffffffffu, v, j);
    bool lower = (i & j) == 0;
    bool desc  = (i & k) == 0;
    bool keep_max = (lower == desc);
    bool pgreater = (p > v);
    return (keep_max == pgreater) ? p : v;
}

// ---------------- hist pass 0: top 8 bits (uint4, match-aggregated) -------
__global__ void __launch_bounds__(256) k_hist0(const float* __restrict__ cls) {
    int img = blockIdx.y;
    int tid = threadIdx.x;
    __shared__ unsigned int sh[256];
    sh[tid] = 0u;
    __syncthreads();
    const uint4* p4 = (const uint4*)(cls + (size_t)img * NPER);
    for (int i = blockIdx.x * 256 + tid; i < N4; i += HB1 * 256) {
        uint4 v = p4[i];
        hadd(sh, v.x >> 24);
        hadd(sh, v.y >> 24);
        hadd(sh, v.z >> 24);
        hadd(sh, v.w >> 24);
    }
    __syncthreads();
    if (sh[tid]) atomicAdd(&g_hist0[img][tid], sh[tid]);
}

// -------- hist pass 1: inline parallel select0, then 2nd-byte hist --------
__global__ void __launch_bounds__(256) k_hist1(const float* __restrict__ cls) {
    int img = blockIdx.y;
    int t = threadIdx.x;
    __shared__ unsigned int cnts[256];
    __shared__ unsigned int sh[256];
    __shared__ unsigned int s_pref, s_krem;

    cnts[t] = g_hist0[img][t];
    sh[t] = 0u;
    __syncthreads();
    suffix_scan256(cnts, t);
    {
        unsigned int St = cnts[t];
        unsigned int Sn = (t == 255) ? 0u : cnts[t + 1];
        if (St >= (unsigned int)PRE && Sn < (unsigned int)PRE) {
            s_pref = (unsigned int)t;
            s_krem = (unsigned int)PRE - Sn;
        }
    }
    __syncthreads();
    unsigned int pref = s_pref;
    if (t == 0) {
        g_pref[img] = pref;
        g_krem[img] = s_krem;
    }

    const uint4* p4 = (const uint4*)(cls + (size_t)img * NPER);
    for (int i = blockIdx.x * 256 + t; i < N4; i += HB1 * 256) {
        uint4 v = p4[i];
        if ((v.x >> 24) == pref) atomicAdd(&sh[(v.x >> 16) & 0xFFu], 1u);
        if ((v.y >> 24) == pref) atomicAdd(&sh[(v.y >> 16) & 0xFFu], 1u);
        if ((v.z >> 24) == pref) atomicAdd(&sh[(v.z >> 16) & 0xFFu], 1u);
        if ((v.w >> 24) == pref) atomicAdd(&sh[(v.w >> 16) & 0xFFu], 1u);
    }
    __syncthreads();
    if (sh[t]) atomicAdd(&g_hist1[img][t], sh[t]);
}

// -------- compact: inline parallel select1 -> 16-bit threshold ------------
__global__ void __launch_bounds__(256) k_compact(const float* __restrict__ cls) {
    int img = blockIdx.y;
    int t = threadIdx.x;
    __shared__ unsigned int cnts[256];
    __shared__ unsigned int s_T;

    cnts[t] = g_hist1[img][t];
    __syncthreads();
    unsigned int krem = g_krem[img];
    unsigned int pref = g_pref[img];
    suffix_scan256(cnts, t);
    {
        unsigned int St = cnts[t];
        unsigned int Sn = (t == 255) ? 0u : cnts[t + 1];
        if (St >= krem && Sn < krem)
            s_T = ((pref << 8) | (unsigned int)t) << 16;
    }
    __syncthreads();
    unsigned int T = s_T;

    const uint4* p4 = (const uint4*)(cls + (size_t)img * NPER);
    for (int i = blockIdx.x * 256 + t; i < N4; i += HB2 * 256) {
        uint4 v = p4[i];
        unsigned int b[4] = {v.x, v.y, v.z, v.w};
        int ib = i * 4;
        #pragma unroll
        for (int u = 0; u < 4; u++) {
            if (b[u] >= T) {
                int idx = ib + u;
                int a = idx / (HH * WW);
                int rem = idx - a * (HH * WW);      // h*W + w
                int r = rem * ANUM + a;              // flattened (h,w,a)
                int pos = atomicAdd(&g_ccnt[img], 1);
                if (pos < CAND_CAP)
                    g_cand[img][pos] =
                        ((unsigned long long)b[u] << 32) | (unsigned int)(~r);
            }
        }
    }
}

// ------- 24-bit trim + hybrid shfl/smem bitonic sort (no props) -----------
__global__ void k_sort() {
    int img = blockIdx.x;
    int tid = threadIdx.x;                 // 1024 threads
    __shared__ unsigned long long s[CAND_CAP];
    __shared__ unsigned int h24[256];
    __shared__ unsigned int segtot[8];
    __shared__ int s_cnt;
    __shared__ unsigned int s_min16, s_above, s_v24, s_tot, s_idx;

    if (tid == 0) {
        s_cnt = g_ccnt[img];
        g_ccnt[img] = 0;                   // reset for next replay (single thread)
        s_min16 = 0xffffffffu;
        s_above = 0u;
        s_v24 = 0u;
        s_tot = 0x7fffffffu;
        s_idx = 0u;
    }
    if (tid < 256) h24[tid] = 0u;
    __syncthreads();
    int cnt = s_cnt;
    if (cnt > CAND_CAP) cnt = CAND_CAP;

    unsigned long long key[4];
    #pragma unroll
    for (int k = 0; k < 4; k++) {
        int i = tid + k * 1024;
        key[k] = (i < cnt) ? g_cand[img][i] : 0ull;
    }

    unsigned int m16 = 0xffffffffu;
    #pragma unroll
    for (int k = 0; k < 4; k++) {
        int i = tid + k * 1024;
        if (i < cnt) {
            unsigned int p = (unsigned int)(key[k] >> 48);
            if (p < m16) m16 = p;
        }
    }
    atomicMin(&s_min16, m16);
    __syncthreads();
    unsigned int min16 = s_min16;

    #pragma unroll
    for (int k = 0; k < 4; k++) {
        int i = tid + k * 1024;
        if (i < cnt) {
            unsigned int p = (unsigned int)(key[k] >> 48);
            if (p == min16) atomicAdd(&h24[(unsigned int)(key[k] >> 40) & 0xFFu], 1u);
            else            atomicAdd(&s_above, 1u);
        }
    }
    __syncthreads();

    // two-level warp suffix scan of h24 (3 syncs instead of 16)
    {
        int w = tid >> 5, lane = tid & 31;
        unsigned int v = 0;
        if (w < 8) {
            v = h24[w * 32 + lane];
            #pragma unroll
            for (int off = 1; off < 32; off <<= 1) {
                unsigned int tt = __shfl_down_sync(0xffffffffu, v, off);
                if (lane + off < 32) v += tt;
            }
            if (lane == 0) segtot[w] = v;   // segment total
        }
        __syncthreads();
        if (tid == 0) {
            unsigned int acc = 0;
            #pragma unroll
            for (int u = 7; u >= 0; u--) {
                unsigned int tt = segtot[u];
                segtot[u] = acc;            // suffix of LATER segments
                acc += tt;
            }
        }
        __syncthreads();
        if (w < 8) h24[w * 32 + lane] = v + segtot[w];
        __syncthreads();
    }

    if (tid < 256) {
        int krem2 = PRE - (int)s_above;
        unsigned int St = h24[tid];
        unsigned int Sn = (tid == 255) ? 0u : h24[tid + 1];
        if (krem2 > 0 && St >= (unsigned int)krem2 && Sn < (unsigned int)krem2) {
            s_v24 = (unsigned int)tid;
            s_tot = s_above + St;
        }
    }
    __syncthreads();

    if (s_tot <= 2048u) {
        unsigned int v24 = s_v24;
        for (int i = tid; i < 2048; i += 1024) s[i] = 0ull;
        __syncthreads();
        #pragma unroll
        for (int k = 0; k < 4; k++) {
            int i = tid + k * 1024;
            if (i < cnt) {
                unsigned int p = (unsigned int)(key[k] >> 48);
                bool keep = (p > min16) ||
                            (((unsigned int)(key[k] >> 40) & 0xFFu) >= v24);
                if (keep) s[atomicAdd(&s_idx, 1u)] = key[k];
            }
        }
        __syncthreads();

        int i0 = tid;
        int i1 = tid + 1024;
        unsigned long long v0 = s[i0];
        unsigned long long v1 = s[i1];

        #pragma unroll
        for (int k = 2; k <= 32; k <<= 1) {
            #pragma unroll
            for (int j = k >> 1; j >= 1; j >>= 1) {
                v0 = bshfl(v0, i0, j, k);
                v1 = bshfl(v1, i1, j, k);
            }
        }
        #pragma unroll
        for (int k = 64; k <= 2048; k <<= 1) {
            s[i0] = v0;
            s[i1] = v1;
            __syncthreads();
            for (int j = k >> 1; j >= 32; j >>= 1) {
                // perfect pair mapping: 1024 threads -> 1024 exchange pairs
                int i = ((tid & ~(j - 1)) << 1) | (tid & (j - 1));
                int ixj = i | j;
                unsigned long long a = s[i], b = s[ixj];
                bool descSeg = ((i & k) == 0);
                if (descSeg ? (a < b) : (a > b)) { s[i] = b; s[ixj] = a; }
                __syncthreads();
            }
            v0 = s[i0];
            v1 = s[i1];
            #pragma unroll
            for (int j = 16; j >= 1; j >>= 1) {
                v0 = bshfl(v0, i0, j, k);
                v1 = bshfl(v1, i1, j, k);
            }
        }
        s[i0] = v0;
        s[i1] = v1;
        __syncthreads();
    } else {
        // fallback: full-smem bitonic (rare)
        #pragma unroll
        for (int k = 0; k < 4; k++) s[tid + k * 1024] = key[k];
        int n = (cnt <= 2048) ? 2048 : 4096;
        __syncthreads();
        for (int k = 2; k <= n; k <<= 1) {
            for (int j = k >> 1; j > 0; j >>= 1) {
                for (int i = tid; i < n; i += 1024) {
                    int ixj = i ^ j;
                    if (ixj > i) {
                        unsigned long long a = s[i], b = s[ixj];
                        bool descSeg = ((i & k) == 0);
                        if (descSeg ? (a < b) : (a > b)) { s[i] = b; s[ixj] = a; }
                    }
                }
                __syncthreads();
            }
        }
    }

    #pragma unroll
    for (int pass = 0; pass < 2; pass++) {
        int i = tid + pass * 1024;
        if (i < PRE) {
            unsigned long long kk = s[i];
            g_tsc[img][i] = __uint_as_float((unsigned int)(kk >> 32));
            g_ridx[img][i] = (int)(~(unsigned int)kk);
        }
    }
}

// ------- bbox transform + clip + validity (wide grid: FP64 spread) --------
__global__ void __launch_bounds__(128) k_props(const float* __restrict__ pred,
                                               const float* __restrict__ iminfo,
                                               const float* __restrict__ anchors) {
    int img = blockIdx.y;
    int i = blockIdx.x * 128 + threadIdx.x;    // < 2048
    bool valid = false;
    float x1 = 0.f, y1 = 0.f, x2 = 0.f, y2 = 0.f, area = 0.f;

    if (i < PRE) {
        int r = g_ridx[img][i];
        int a = r % ANUM;
        int t2 = r / ANUM;
        int w = t2 % WW;
        int h = t2 / WW;

        float sx = (float)w * STRIDEF;
        float sy = (float)h * STRIDEF;
        float ax1 = __fadd_rn(anchors[a * 4 + 0], sx);
        float ay1 = __fadd_rn(anchors[a * 4 + 1], sy);
        float ax2 = __fadd_rn(anchors[a * 4 + 2], sx);
        float ay2 = __fadd_rn(anchors[a * 4 + 3], sy);

        float ws = __fadd_rn(__fsub_rn(ax2, ax1), 1.0f);
        float hs = __fadd_rn(__fsub_rn(ay2, ay1), 1.0f);
        float cx = __fadd_rn(ax1, __fmul_rn(0.5f, ws));
        float cy = __fadd_rn(ay1, __fmul_rn(0.5f, hs));

        size_t bidx = (((size_t)img * (4 * ANUM) + 4 * a) * HH + h) * WW + w;
        float dx = pred[bidx];
        float dy = pred[bidx + (size_t)HH * WW];
        float dw = pred[bidx + 2 * (size_t)HH * WW];
        float dh = pred[bidx + 3 * (size_t)HH * WW];
        const float XCLIP = 4.135166556742356f; // log(1000/16)
        dw = fminf(dw, XCLIP);
        dh = fminf(dh, XCLIP);

        float pcx = __fadd_rn(__fmul_rn(dx, ws), cx);
        float pcy = __fadd_rn(__fmul_rn(dy, hs), cy);
        float ew = (float)exp((double)dw);     // double exp -> correctly rounded f32
        float eh = (float)exp((double)dh);
        float pw = __fmul_rn(ew, ws);
        float ph = __fmul_rn(eh, hs);

        x1 = __fsub_rn(pcx, __fmul_rn(0.5f, pw));
        y1 = __fsub_rn(pcy, __fmul_rn(0.5f, ph));
        x2 = __fsub_rn(__fadd_rn(pcx, __fmul_rn(0.5f, pw)), 1.0f);
        y2 = __fsub_rn(__fadd_rn(pcy, __fmul_rn(0.5f, ph)), 1.0f);

        float im_h = iminfo[img * 3 + 0];
        float im_w = iminfo[img * 3 + 1];
        float scale = iminfo[img * 3 + 2];
        float wmax = __fsub_rn(im_w, 1.0f);
        float hmax = __fsub_rn(im_h, 1.0f);
        x1 = fminf(fmaxf(x1, 0.0f), wmax);
        y1 = fminf(fmaxf(y1, 0.0f), hmax);
        x2 = fminf(fmaxf(x2, 0.0f), wmax);
        y2 = fminf(fmaxf(y2, 0.0f), hmax);

        float ws2 = __fadd_rn(__fsub_rn(x2, x1), 1.0f);
        float hs2 = __fadd_rn(__fsub_rn(y2, y1), 1.0f);
        float ms = __fmul_rn(0.0f, scale);     // MIN_SIZE = 0
        valid = (ws2 >= ms) & (hs2 >= ms)
              & (__fadd_rn(x1, __fmul_rn(ws2, 0.5f)) < im_w)
              & (__fadd_rn(y1, __fmul_rn(hs2, 0.5f)) < im_h);
        area = __fmul_rn(ws2, hs2);
    }

    unsigned int bm = __ballot_sync(0xffffffffu, valid);
    if ((threadIdx.x & 31) == 0) g_valmask32[img][i >> 5] = bm;
    if (i < PRE) {
        g_box[img][i]  = make_float4(x1, y1, x2, y2);
        g_boxn[img][i] = make_float4(-x1, -y1, x2, y2);
        g_area[img][i] = area;
        g_a07[img][i]  = __fmul_rn(0.7f, area);
    }
}

// -------- NMS bitmask: branch-free screen + post-loop exact fixup ----------
__global__ void k_nmsmask() {
    int img = blockIdx.z;
    int rt = blockIdx.y;
    int cb = blockIdx.x;
    int t = threadIdx.x;                 // 0..63
    int j0 = cb * 64;
    int rbase = rt * ROWT;

    if (j0 + 64 <= rbase) {
        #pragma unroll
        for (int r = 0; r < 4; r++) {
            int i = rbase + r * 64 + t;
            if (i < PRE) g_mask[img][i][cb] = 0ull;
        }
        return;
    }

    __shared__ float4 cb4[64];
    __shared__ float  ca[64];
    __shared__ float  c07[64];
    int j = j0 + t;
    if (j < PRE) {
        cb4[t] = g_boxn[img][j];
        ca[t]  = g_area[img][j];
        c07[t] = g_a07[img][j];
    } else {
        cb4[t] = make_float4(-1e30f, -1e30f, -1e30f, -1e30f);
        ca[t]  = 1.0f;
        c07[t] = 0.7f;
    }
    __syncthreads();

    float4 rb[4];
    float  ra[4], r07[4];
    int    ri[4];
    #pragma unroll
    for (int r = 0; r < 4; r++) {
        ri[r] = rbase + r * 64 + t;
        if (ri[r] < PRE) {
            rb[r]  = g_boxn[img][ri[r]];
            ra[r]  = g_area[img][ri[r]];
            r07[r] = g_a07[img][ri[r]];
        } else {
            rb[r]  = make_float4(-1e30f, -1e30f, -1e30f, -1e30f);
            ra[r]  = 1.0f;
            r07[r] = 0.7f;
        }
    }

    unsigned long long bits[4] = {0ull, 0ull, 0ull, 0ull};
    unsigned long long rare[4] = {0ull, 0ull, 0ull, 0ull};

    #pragma unroll 4
    for (int q = 0; q < 64; q++) {
        float4 c = cb4[q];
        float c07q = c07[q];
        unsigned long long m64 = 1ull << q;
        #pragma unroll
        for (int r = 0; r < 4; r++) {
            float e1 = fminf(rb[r].z, c.z);
            float e2 = fminf(rb[r].x, c.x);
            float iw = fmaxf(__fadd_rn(__fadd_rn(e1, e2), 1.0f), 0.0f);
            float e3 = fminf(rb[r].w, c.w);
            float e4 = fminf(rb[r].y, c.y);
            float ih = fmaxf(__fadd_rn(__fadd_rn(e3, e4), 1.0f), 0.0f);
            float inter = __fmul_rn(iw, ih);
            float s07 = __fadd_rn(r07[r], c07q);
            float d2 = __fmaf_rn(1.7f, inter, -s07);
            float th = __fmul_rn(s07, 1e-5f);
            bool sup = (d2 > 0.0f);
            bool isr = !(fabsf(d2) > th) || (s07 <= 0.0f);
            if (sup) bits[r] |= m64;
            if (isr) rare[r] |= m64;
        }
    }

    // exact reference-order fixup for pairs inside the screen band (rare)
    #pragma unroll
    for (int r = 0; r < 4; r++) {
        while (rare[r]) {
            int q = __ffsll((long long)rare[r]) - 1;
            rare[r] &= rare[r] - 1ull;
            float4 c = cb4[q];
            float e1 = fminf(rb[r].z, c.z);
            float e2 = fminf(rb[r].x, c.x);
            float iw = fmaxf(__fadd_rn(__fadd_rn(e1, e2), 1.0f), 0.0f);
            float e3 = fminf(rb[r].w, c.w);
            float e4 = fminf(rb[r].y, c.y);
            float ih = fmaxf(__fadd_rn(__fadd_rn(e3, e4), 1.0f), 0.0f);
            float inter = __fmul_rn(iw, ih);
            float denom = __fsub_rn(__fadd_rn(ra[r], ca[q]), inter);
            bool sup = (__fdiv_rn(inter, denom) > 0.7f);
            unsigned long long m64 = 1ull << q;
            if (sup) bits[r] |= m64;
            else     bits[r] &= ~m64;
        }
    }

    int colend = PRE - j0;
    unsigned long long colmask = (colend >= 64) ? ~0ull : ((1ull << colend) - 1ull);
    #pragma unroll
    for (int r = 0; r < 4; r++) {
        int i = ri[r];
        if (i < PRE) {
            unsigned long long m = bits[r] & colmask;
            if (i >= j0) {
                int low = i - j0 + 1;
                m = (low >= 64) ? 0ull : (m & ~((1ull << low) - 1ull));
            }
            g_mask[img][i][cb] = m;
        }
    }
}

// ------- fused: branchless greedy reduce (warp 0) + early exit + output ----
__global__ void __launch_bounds__(256) k_reduce_out(float* __restrict__ out) {
    int img = blockIdx.x;
    int tid = threadIdx.x;
    __shared__ unsigned long long skw[NWORDS];
    __shared__ int woff[NWORDS + 1];

    // re-zero histograms for the next replay (independent of reduce)
    if (tid < 64) ((uint4*)g_hist0[img])[tid] = make_uint4(0u, 0u, 0u, 0u);
    else if (tid < 128) ((uint4*)g_hist1[img])[tid - 64] = make_uint4(0u, 0u, 0u, 0u);

    if (tid < 32) {
        int t = tid;
        unsigned int v0 = g_valmask32[img][2 * t];
        unsigned int v1 = g_valmask32[img][2 * t + 1];
        unsigned long long rem = ~(((unsigned long long)v1 << 32) | (unsigned long long)v0);

        const unsigned long long* mrow = &g_mask[img][0][t];

        unsigned long long buf[16];
        #pragma unroll
        for (int k = 0; k < 16; k++) buf[k] = mrow[k * 32];

        unsigned long long keepw = 0ull;
        unsigned long long cur = __shfl_sync(0xffffffffu, rem, 0);
        int kept = 0;
        bool done = false;

        for (int g = 0; g < 125 && !done; g++) {
            unsigned long long nbuf[16];
            if (g < 124) {
                #pragma unroll
                for (int k = 0; k < 16; k++) nbuf[k] = mrow[(g + 1) * 512 + k * 32];
            }
            int gb = g * 16;
            int c = gb >> 6;
            #pragma unroll
            for (int k = 0; k < 16; k++) {
                int q = (gb + k) & 63;
                unsigned long long mb = __shfl_sync(0xffffffffu, buf[k], c);
                unsigned long long bitv = (cur >> q) & 1ull;     // 1 = suppressed
                unsigned long long km = bitv - 1ull;             // ~0 if keep
                cur |= mb & km;
                rem |= buf[k] & km;
                keepw |= (1ull << q) & km;
            }
            if (((gb + 16) & 63) == 0) {     // end of 64-bit chunk c
                if (t == 0) skw[c] = keepw;
                kept += __popcll(keepw);
                keepw = 0ull;
                if (kept >= POST) {          // rest cannot change output
                    for (int w = c + 1 + t; w < NWORDS; w += 32) skw[w] = 0ull;
                    done = true;
                } else if (c + 1 < NWORDS) {
                    cur = __shfl_sync(0xffffffffu, rem, c + 1);
                }
            }
            #pragma unroll
            for (int k = 0; k < 16; k++) buf[k] = nbuf[k];
        }
        if (!done && t == 0) skw[31] = keepw;
    }
    __syncthreads();

    if (tid < 32) {
        int x = __popcll(skw[tid]);
        #pragma unroll
        for (int o = 1; o < 32; o <<= 1) {
            int y = __shfl_up_sync(0xffffffffu, x, o);
            if (tid >= o) x += y;
        }
        woff[tid + 1] = x;
        if (tid == 0) woff[0] = 0;
    }
    __syncthreads();

    int total = woff[NWORDS];
    if (total > POST) total = POST;

    float* rois = out;
    float* probs = out + (size_t)BATCH * POST * 5;

    for (int i = tid; i < PRE; i += blockDim.x) {
        unsigned long long w = skw[i >> 6];
        if ((w >> (i & 63)) & 1ull) {
            int s = woff[i >> 6] + __popcll(w & ((1ull << (i & 63)) - 1ull));
            if (s < POST) {
                float4 b = g_box[img][i];
                size_t row = (size_t)(img * POST + s) * 5;
                rois[row + 0] = (float)img;
                rois[row + 1] = b.x;
                rois[row + 2] = b.y;
                rois[row + 3] = b.z;
                rois[row + 4] = b.w;
                probs[img * POST + s] = g_tsc[img][i];
            }
        }
    }
    for (int s = total + tid; s < POST; s += blockDim.x) {
        size_t row = (size_t)(img * POST + s) * 5;
        rois[row + 0] = (float)img;
        rois[row + 1] = 0.0f;
        rois[row + 2] = 0.0f;
        rois[row + 3] = 0.0f;
        rois[row + 4] = 0.0f;
        probs[img * POST + s] = 0.0f;
    }
}

// ---------------- launch ----------------
extern "C" void kernel_launch(void* const* d_in, const int* in_sizes, int n_in,
                              void* d_out, int out_size) {
    const float* cls     = (const float*)d_in[0];
    const float* pred    = (const float*)d_in[1];
    const float* iminfo  = (const float*)d_in[2];
    const float* anchors = (const float*)d_in[3];
    float* out = (float*)d_out;

    k_hist0<<<dim3(HB1, BATCH), 256>>>(cls);
    k_hist1<<<dim3(HB1, BATCH), 256>>>(cls);
    k_compact<<<dim3(HB2, BATCH), 256>>>(cls);
    k_sort<<<BATCH, 1024>>>();
    k_props<<<dim3(16, BATCH), 128>>>(pred, iminfo, anchors);
    k_nmsmask<<<dim3(NWORDS, (PRE + ROWT - 1) / ROWT, BATCH), 64>>>();
    k_reduce_out<<<BATCH, 256>>>(out);
}

// round 15
// speedup vs baseline: 1.0049x; 1.0049x over previous
#include <cuda_runtime.h>
#include <math.h>
#include <stdint.h>

#define BATCH 8
#define ANUM 15
#define HH 100
#define WW 168
#define NPER (ANUM*HH*WW)      // 252000
#define N4 (NPER/4)            // 63000
#define PRE 2000
#define POST 1000
#define CAND_CAP 4096
#define NWORDS 32              // ceil(PRE/64)
#define ROWT 256               // rows per nms tile
#define STRIDEF 8.0f
#define TBX 64                 // blocks per image in k_topk
#define TOPK_NB (TBX*BATCH)    // 512 blocks total (<= 4/SM * 148 = 592)

// ---------------- scratch (no allocations allowed) ----------------
__device__ unsigned int       g_hist0[BATCH][256];   // zeroed by k_reduce_out
__device__ unsigned int       g_hist1[BATCH][256];
__device__ unsigned long long g_cand[BATCH][CAND_CAP];
__device__ int                g_ccnt[BATCH];         // read+reset by tid0 of k_sort
__device__ float              g_tsc[BATCH][PRE];
__device__ int                g_ridx[BATCH][PRE];    // sorted anchor indices
__device__ float4             g_box[BATCH][PRE];     // (x1,y1,x2,y2) output
__device__ float4             g_boxn[BATCH][PRE];    // (-x1,-y1,x2,y2) for IoU
__device__ float              g_area[BATCH][PRE];    // exact reference-order area
__device__ float              g_a07[BATCH][PRE];     // 0.7f * area
__device__ unsigned int       g_valmask32[BATCH][64];
__device__ unsigned long long g_mask[BATCH][PRE][NWORDS];   // 4 MB
__device__ unsigned int       g_barcnt;
__device__ unsigned int       g_bargen;   // monotonic across replays

// ---------------- grid barrier (all TOPK_NB blocks co-resident) ----------
__device__ __forceinline__ void grid_barrier(unsigned int base, unsigned int k) {
    __syncthreads();
    if (threadIdx.x == 0) {
        __threadfence();
        unsigned int old = atomicAdd(&g_barcnt, 1u);
        if (old == TOPK_NB - 1u) {
            atomicExch(&g_barcnt, 0u);
            __threadfence();
            atomicAdd(&g_bargen, 1u);
        } else {
            unsigned int cur;
            do {
                __nanosleep(64);
                asm volatile("ld.acquire.gpu.u32 %0, [%1];"
                             : "=r"(cur) : "l"(&g_bargen) : "memory");
            } while ((int)(cur - (base + k)) < 0);
        }
    }
    __syncthreads();
}

__device__ __forceinline__ void suffix_scan256(unsigned int* cnts, int t) {
    #pragma unroll
    for (int off = 1; off < 256; off <<= 1) {
        unsigned int add = (t + off < 256) ? cnts[t + off] : 0u;
        __syncthreads();
        cnts[t] += add;
        __syncthreads();
    }
}

// warp-aggregated histogram add: one atomic per distinct bin per warp step
__device__ __forceinline__ void hadd(unsigned int* sh, unsigned int bin) {
    unsigned int am = __activemask();
    unsigned int m = __match_any_sync(am, bin);
    int leader = __ffs(m) - 1;
    if ((int)(threadIdx.x & 31) == leader) atomicAdd(&sh[bin], __popc(m));
}

// bitonic compare-exchange via warp shuffle (stride j <= 16)
__device__ __forceinline__ unsigned long long bshfl(
    unsigned long long v, int i, int j, int k) {
    unsigned long long p = __shfl_xor_sync(0xffffffffu, v, j);
    bool lower = (i & j) == 0;
    bool desc  = (i & k) == 0;
    bool keep_max = (lower == desc);
    bool pgreater = (p > v);
    return (keep_max == pgreater) ? p : v;
}

// ----- fused top-k: registers hold the slice; 2 grid barriers, 0 re-reads --
__global__ void __launch_bounds__(256, 4) k_topk(const float* __restrict__ cls) {
    int img = blockIdx.y;
    int blk = blockIdx.x;                  // 0..TBX-1
    int tid = threadIdx.x;
    __shared__ unsigned int sh[256];
    __shared__ unsigned int cnts[256];
    __shared__ unsigned int s_base, s_pref, s_krem, s_T;

    if (tid == 0) s_base = *(volatile unsigned int*)&g_bargen;
    sh[tid] = 0u;
    __syncthreads();
    unsigned int base = s_base;

    // ---- load this thread's slice into registers (entire tensor held) ----
    const uint4* p4 = (const uint4*)(cls + (size_t)img * NPER);
    uint4 val[4];
    bool  ok[4];
    #pragma unroll
    for (int c = 0; c < 4; c++) {
        int i = blk * 256 + tid + c * (TBX * 256);
        ok[c] = (i < N4);
        val[c] = ok[c] ? p4[i] : make_uint4(0u, 0u, 0u, 0u);
    }

    // ---- coarse 8-bit histogram (warp-aggregated) ----
    #pragma unroll
    for (int c = 0; c < 4; c++) {
        if (ok[c]) {
            hadd(sh, val[c].x >> 24);
            hadd(sh, val[c].y >> 24);
            hadd(sh, val[c].z >> 24);
            hadd(sh, val[c].w >> 24);
        }
    }
    __syncthreads();
    if (sh[tid]) atomicAdd(&g_hist0[img][tid], sh[tid]);
    grid_barrier(base, 1);

    // ---- select0 (every block, redundant) ----
    cnts[tid] = __ldcg(&g_hist0[img][tid]);
    sh[tid] = 0u;
    __syncthreads();
    suffix_scan256(cnts, tid);
    {
        unsigned int St = cnts[tid];
        unsigned int Sn = (tid == 255) ? 0u : cnts[tid + 1];
        if (St >= (unsigned int)PRE && Sn < (unsigned int)PRE) {
            s_pref = (unsigned int)tid;
            s_krem = (unsigned int)PRE - Sn;
        }
    }
    __syncthreads();
    unsigned int pref = s_pref;
    unsigned int krem = s_krem;

    // ---- fine 8-bit histogram within pref (from registers) ----
    #pragma unroll
    for (int c = 0; c < 4; c++) {
        if (ok[c]) {
            if ((val[c].x >> 24) == pref) atomicAdd(&sh[(val[c].x >> 16) & 0xFFu], 1u);
            if ((val[c].y >> 24) == pref) atomicAdd(&sh[(val[c].y >> 16) & 0xFFu], 1u);
            if ((val[c].z >> 24) == pref) atomicAdd(&sh[(val[c].z >> 16) & 0xFFu], 1u);
            if ((val[c].w >> 24) == pref) atomicAdd(&sh[(val[c].w >> 16) & 0xFFu], 1u);
        }
    }
    __syncthreads();
    if (sh[tid]) atomicAdd(&g_hist1[img][tid], sh[tid]);
    grid_barrier(base, 2);

    // ---- select1 -> 16-bit threshold (every block, redundant) ----
    cnts[tid] = __ldcg(&g_hist1[img][tid]);
    __syncthreads();
    suffix_scan256(cnts, tid);
    {
        unsigned int St = cnts[tid];
        unsigned int Sn = (tid == 255) ? 0u : cnts[tid + 1];
        if (St >= krem && Sn < krem)
            s_T = ((pref << 8) | (unsigned int)tid) << 16;
    }
    __syncthreads();
    unsigned int T = s_T;

    // ---- compact from registers ----
    #pragma unroll
    for (int c = 0; c < 4; c++) {
        if (!ok[c]) continue;
        int ib = (blk * 256 + tid + c * (TBX * 256)) * 4;
        unsigned int b[4] = {val[c].x, val[c].y, val[c].z, val[c].w};
        #pragma unroll
        for (int u = 0; u < 4; u++) {
            if (b[u] >= T) {
                int idx = ib + u;
                int a = idx / (HH * WW);
                int rem = idx - a * (HH * WW);      // h*W + w
                int r = rem * ANUM + a;              // flattened (h,w,a)
                int pos = atomicAdd(&g_ccnt[img], 1);
                if (pos < CAND_CAP)
                    g_cand[img][pos] =
                        ((unsigned long long)b[u] << 32) | (unsigned int)(~r);
            }
        }
    }
}

// ------- 24-bit trim + hybrid shfl/smem bitonic sort (no props) -----------
__global__ void k_sort() {
    int img = blockIdx.x;
    int tid = threadIdx.x;                 // 1024 threads
    __shared__ unsigned long long s[CAND_CAP];
    __shared__ unsigned int h24[256];
    __shared__ int s_cnt;
    __shared__ unsigned int s_min16, s_above, s_v24, s_tot, s_idx;

    if (tid == 0) {
        s_cnt = g_ccnt[img];
        g_ccnt[img] = 0;                   // reset for next replay (single thread)
        s_min16 = 0xffffffffu;
        s_above = 0u;
        s_v24 = 0u;
        s_tot = 0x7fffffffu;
        s_idx = 0u;
    }
    if (tid < 256) h24[tid] = 0u;
    __syncthreads();
    int cnt = s_cnt;
    if (cnt > CAND_CAP) cnt = CAND_CAP;

    unsigned long long key[4];
    #pragma unroll
    for (int k = 0; k < 4; k++) {
        int i = tid + k * 1024;
        key[k] = (i < cnt) ? g_cand[img][i] : 0ull;
    }

    unsigned int m16 = 0xffffffffu;
    #pragma unroll
    for (int k = 0; k < 4; k++) {
        int i = tid + k * 1024;
        if (i < cnt) {
            unsigned int p = (unsigned int)(key[k] >> 48);
            if (p < m16) m16 = p;
        }
    }
    atomicMin(&s_min16, m16);
    __syncthreads();
    unsigned int min16 = s_min16;

    #pragma unroll
    for (int k = 0; k < 4; k++) {
        int i = tid + k * 1024;
        if (i < cnt) {
            unsigned int p = (unsigned int)(key[k] >> 48);
            if (p == min16) atomicAdd(&h24[(unsigned int)(key[k] >> 40) & 0xFFu], 1u);
            else            atomicAdd(&s_above, 1u);
        }
    }
    __syncthreads();
    #pragma unroll
    for (int off = 1; off < 256; off <<= 1) {
        unsigned int add = (tid < 256 && tid + off < 256) ? h24[tid + off] : 0u;
        __syncthreads();
        if (tid < 256) h24[tid] += add;
        __syncthreads();
    }
    if (tid < 256) {
        int krem2 = PRE - (int)s_above;
        unsigned int St = h24[tid];
        unsigned int Sn = (tid == 255) ? 0u : h24[tid + 1];
        if (krem2 > 0 && St >= (unsigned int)krem2 && Sn < (unsigned int)krem2) {
            s_v24 = (unsigned int)tid;
            s_tot = s_above + St;
        }
    }
    __syncthreads();

    if (s_tot <= 2048u) {
        unsigned int v24 = s_v24;
        for (int i = tid; i < 2048; i += 1024) s[i] = 0ull;
        __syncthreads();
        #pragma unroll
        for (int k = 0; k < 4; k++) {
            int i = tid + k * 1024;
            if (i < cnt) {
                unsigned int p = (unsigned int)(key[k] >> 48);
                bool keep = (p > min16) ||
                            (((unsigned int)(key[k] >> 40) & 0xFFu) >= v24);
                if (keep) s[atomicAdd(&s_idx, 1u)] = key[k];
            }
        }
        __syncthreads();

        int i0 = tid;
        int i1 = tid + 1024;
        unsigned long long v0 = s[i0];
        unsigned long long v1 = s[i1];

        #pragma unroll
        for (int k = 2; k <= 32; k <<= 1) {
            #pragma unroll
            for (int j = k >> 1; j >= 1; j >>= 1) {
                v0 = bshfl(v0, i0, j, k);
                v1 = bshfl(v1, i1, j, k);
            }
        }
        #pragma unroll
        for (int k = 64; k <= 2048; k <<= 1) {
            s[i0] = v0;
            s[i1] = v1;
            __syncthreads();
            for (int j = k >> 1; j >= 32; j >>= 1) {
                int i = ((tid & ~(j - 1)) << 1) | (tid & (j - 1));
                int ixj = i | j;
                unsigned long long a = s[i], b = s[ixj];
                bool descSeg = ((i & k) == 0);
                if (descSeg ? (a < b) : (a > b)) { s[i] = b; s[ixj] = a; }
                __syncthreads();
            }
            v0 = s[i0];
            v1 = s[i1];
            #pragma unroll
            for (int j = 16; j >= 1; j >>= 1) {
                v0 = bshfl(v0, i0, j, k);
                v1 = bshfl(v1, i1, j, k);
            }
        }
        s[i0] = v0;
        s[i1] = v1;
        __syncthreads();
    } else {
        // fallback: full-smem bitonic (rare)
        #pragma unroll
        for (int k = 0; k < 4; k++) s[tid + k * 1024] = key[k];
        int n = (cnt <= 2048) ? 2048 : 4096;
        __syncthreads();
        for (int k = 2; k <= n; k <<= 1) {
            for (int j = k >> 1; j > 0; j >>= 1) {
                for (int i = tid; i < n; i += 1024) {
                    int ixj = i ^ j;
                    if (ixj > i) {
                        unsigned long long a = s[i], b = s[ixj];
                        bool descSeg = ((i & k) == 0);
                        if (descSeg ? (a < b) : (a > b)) { s[i] = b; s[ixj] = a; }
                    }
                }
                __syncthreads();
            }
        }
    }

    #pragma unroll
    for (int pass = 0; pass < 2; pass++) {
        int i = tid + pass * 1024;
        if (i < PRE) {
            unsigned long long kk = s[i];
            g_tsc[img][i] = __uint_as_float((unsigned int)(kk >> 32));
            g_ridx[img][i] = (int)(~(unsigned int)kk);
        }
    }
}

// ------- bbox transform + clip + validity (wide grid: FP64 spread) --------
__global__ void __launch_bounds__(256) k_props(const float* __restrict__ pred,
                                               const float* __restrict__ iminfo,
                                               const float* __restrict__ anchors) {
    int img = blockIdx.y;
    int i = blockIdx.x * 256 + threadIdx.x;    // < 2048
    bool valid = false;
    float x1 = 0.f, y1 = 0.f, x2 = 0.f, y2 = 0.f, area = 0.f;

    if (i < PRE) {
        int r = g_ridx[img][i];
        int a = r % ANUM;
        int t2 = r / ANUM;
        int w = t2 % WW;
        int h = t2 / WW;

        float sx = (float)w * STRIDEF;
        float sy = (float)h * STRIDEF;
        float ax1 = __fadd_rn(anchors[a * 4 + 0], sx);
        float ay1 = __fadd_rn(anchors[a * 4 + 1], sy);
        float ax2 = __fadd_rn(anchors[a * 4 + 2], sx);
        float ay2 = __fadd_rn(anchors[a * 4 + 3], sy);

        float ws = __fadd_rn(__fsub_rn(ax2, ax1), 1.0f);
        float hs = __fadd_rn(__fsub_rn(ay2, ay1), 1.0f);
        float cx = __fadd_rn(ax1, __fmul_rn(0.5f, ws));
        float cy = __fadd_rn(ay1, __fmul_rn(0.5f, hs));

        size_t bidx = (((size_t)img * (4 * ANUM) + 4 * a) * HH + h) * WW + w;
        float dx = pred[bidx];
        float dy = pred[bidx + (size_t)HH * WW];
        float dw = pred[bidx + 2 * (size_t)HH * WW];
        float dh = pred[bidx + 3 * (size_t)HH * WW];
        const float XCLIP = 4.135166556742356f; // log(1000/16)
        dw = fminf(dw, XCLIP);
        dh = fminf(dh, XCLIP);

        float pcx = __fadd_rn(__fmul_rn(dx, ws), cx);
        float pcy = __fadd_rn(__fmul_rn(dy, hs), cy);
        float ew = (float)exp((double)dw);     // double exp -> correctly rounded f32
        float eh = (float)exp((double)dh);
        float pw = __fmul_rn(ew, ws);
        float ph = __fmul_rn(eh, hs);

        x1 = __fsub_rn(pcx, __fmul_rn(0.5f, pw));
        y1 = __fsub_rn(pcy, __fmul_rn(0.5f, ph));
        x2 = __fsub_rn(__fadd_rn(pcx, __fmul_rn(0.5f, pw)), 1.0f);
        y2 = __fsub_rn(__fadd_rn(pcy, __fmul_rn(0.5f, ph)), 1.0f);

        float im_h = iminfo[img * 3 + 0];
        float im_w = iminfo[img * 3 + 1];
        float scale = iminfo[img * 3 + 2];
        float wmax = __fsub_rn(im_w, 1.0f);
        float hmax = __fsub_rn(im_h, 1.0f);
        x1 = fminf(fmaxf(x1, 0.0f), wmax);
        y1 = fminf(fmaxf(y1, 0.0f), hmax);
        x2 = fminf(fmaxf(x2, 0.0f), wmax);
        y2 = fminf(fmaxf(y2, 0.0f), hmax);

        float ws2 = __fadd_rn(__fsub_rn(x2, x1), 1.0f);
        float hs2 = __fadd_rn(__fsub_rn(y2, y1), 1.0f);
        float ms = __fmul_rn(0.0f, scale);     // MIN_SIZE = 0
        valid = (ws2 >= ms) & (hs2 >= ms)
              & (__fadd_rn(x1, __fmul_rn(ws2, 0.5f)) < im_w)
              & (__fadd_rn(y1, __fmul_rn(hs2, 0.5f)) < im_h);
        area = __fmul_rn(ws2, hs2);
    }

    unsigned int bm = __ballot_sync(0xffffffffu, valid);
    if ((threadIdx.x & 31) == 0) g_valmask32[img][i >> 5] = bm;
    if (i < PRE) {
        g_box[img][i]  = make_float4(x1, y1, x2, y2);
        g_boxn[img][i] = make_float4(-x1, -y1, x2, y2);
        g_area[img][i] = area;
        g_a07[img][i]  = __fmul_rn(0.7f, area);
    }
}

// -------- NMS bitmask: branch-free screen + post-loop exact fixup ----------
__global__ void k_nmsmask() {
    int img = blockIdx.z;
    int rt = blockIdx.y;
    int cb = blockIdx.x;
    int t = threadIdx.x;                 // 0..63
    int j0 = cb * 64;
    int rbase = rt * ROWT;

    if (j0 + 64 <= rbase) {
        #pragma unroll
        for (int r = 0; r < 4; r++) {
            int i = rbase + r * 64 + t;
            if (i < PRE) g_mask[img][i][cb] = 0ull;
        }
        return;
    }

    __shared__ float4 cb4[64];
    __shared__ float  ca[64];
    __shared__ float  c07[64];
    int j = j0 + t;
    if (j < PRE) {
        cb4[t] = g_boxn[img][j];
        ca[t]  = g_area[img][j];
        c07[t] = g_a07[img][j];
    } else {
        cb4[t] = make_float4(-1e30f, -1e30f, -1e30f, -1e30f);
        ca[t]  = 1.0f;
        c07[t] = 0.7f;
    }
    __syncthreads();

    float4 rb[4];
    float  ra[4], r07[4];
    int    ri[4];
    #pragma unroll
    for (int r = 0; r < 4; r++) {
        ri[r] = rbase + r * 64 + t;
        if (ri[r] < PRE) {
            rb[r]  = g_boxn[img][ri[r]];
            ra[r]  = g_area[img][ri[r]];
            r07[r] = g_a07[img][ri[r]];
        } else {
            rb[r]  = make_float4(-1e30f, -1e30f, -1e30f, -1e30f);
            ra[r]  = 1.0f;
            r07[r] = 0.7f;
        }
    }

    unsigned long long bits[4] = {0ull, 0ull, 0ull, 0ull};
    unsigned long long rare[4] = {0ull, 0ull, 0ull, 0ull};

    #pragma unroll 4
    for (int q = 0; q < 64; q++) {
        float4 c = cb4[q];
        float c07q = c07[q];
        unsigned long long m64 = 1ull << q;
        #pragma unroll
        for (int r = 0; r < 4; r++) {
            float e1 = fminf(rb[r].z, c.z);
            float e2 = fminf(rb[r].x, c.x);
            float iw = fmaxf(__fadd_rn(__fadd_rn(e1, e2), 1.0f), 0.0f);
            float e3 = fminf(rb[r].w, c.w);
            float e4 = fminf(rb[r].y, c.y);
            float ih = fmaxf(__fadd_rn(__fadd_rn(e3, e4), 1.0f), 0.0f);
            float inter = __fmul_rn(iw, ih);
            float s07 = __fadd_rn(r07[r], c07q);
            float d2 = __fmaf_rn(1.7f, inter, -s07);
            float th = __fmul_rn(s07, 1e-5f);
            bool sup = (d2 > 0.0f);
            bool isr = !(fabsf(d2) > th) || (s07 <= 0.0f);
            if (sup) bits[r] |= m64;
            if (isr) rare[r] |= m64;
        }
    }

    // exact reference-order fixup for pairs inside the screen band (rare)
    #pragma unroll
    for (int r = 0; r < 4; r++) {
        while (rare[r]) {
            int q = __ffsll((long long)rare[r]) - 1;
            rare[r] &= rare[r] - 1ull;
            float4 c = cb4[q];
            float e1 = fminf(rb[r].z, c.z);
            float e2 = fminf(rb[r].x, c.x);
            float iw = fmaxf(__fadd_rn(__fadd_rn(e1, e2), 1.0f), 0.0f);
            float e3 = fminf(rb[r].w, c.w);
            float e4 = fminf(rb[r].y, c.y);
            float ih = fmaxf(__fadd_rn(__fadd_rn(e3, e4), 1.0f), 0.0f);
            float inter = __fmul_rn(iw, ih);
            float denom = __fsub_rn(__fadd_rn(ra[r], ca[q]), inter);
            bool sup = (__fdiv_rn(inter, denom) > 0.7f);
            unsigned long long m64 = 1ull << q;
            if (sup) bits[r] |= m64;
            else     bits[r] &= ~m64;
        }
    }

    int colend = PRE - j0;
    unsigned long long colmask = (colend >= 64) ? ~0ull : ((1ull << colend) - 1ull);
    #pragma unroll
    for (int r = 0; r < 4; r++) {
        int i = ri[r];
        if (i < PRE) {
            unsigned long long m = bits[r] & colmask;
            if (i >= j0) {
                int low = i - j0 + 1;
                m = (low >= 64) ? 0ull : (m & ~((1ull << low) - 1ull));
            }
            g_mask[img][i][cb] = m;
        }
    }
}

// ------- fused: branchless greedy reduce (warp 0) + early exit + output ----
__global__ void __launch_bounds__(256) k_reduce_out(float* __restrict__ out) {
    int img = blockIdx.x;
    int tid = threadIdx.x;
    __shared__ unsigned long long skw[NWORDS];
    __shared__ int woff[NWORDS + 1];

    // re-zero histograms for the next replay (after all k_topk reads)
    if (tid < 64) ((uint4*)g_hist0[img])[tid] = make_uint4(0u, 0u, 0u, 0u);
    else if (tid < 128) ((uint4*)g_hist1[img])[tid - 64] = make_uint4(0u, 0u, 0u, 0u);

    if (tid < 32) {
        int t = tid;
        unsigned int v0 = g_valmask32[img][2 * t];
        unsigned int v1 = g_valmask32[img][2 * t + 1];
        unsigned long long rem = ~(((unsigned long long)v1 << 32) | (unsigned long long)v0);

        const unsigned long long* mrow = &g_mask[img][0][t];

        unsigned long long buf[16];
        #pragma unroll
        for (int k = 0; k < 16; k++) buf[k] = mrow[k * 32];

        unsigned long long keepw = 0ull;
        unsigned long long cur = __shfl_sync(0xffffffffu, rem, 0);
        int kept = 0;
        bool done = false;

        for (int g = 0; g < 125 && !done; g++) {
            unsigned long long nbuf[16];
            if (g < 124) {
                #pragma unroll
                for (int k = 0; k < 16; k++) nbuf[k] = mrow[(g + 1) * 512 + k * 32];
            }
            int gb = g * 16;
            int c = gb >> 6;
            #pragma unroll
            for (int k = 0; k < 16; k++) {
                int q = (gb + k) & 63;
                unsigned long long mb = __shfl_sync(0xffffffffu, buf[k], c);
                unsigned long long bitv = (cur >> q) & 1ull;     // 1 = suppressed
                unsigned long long km = bitv - 1ull;             // ~0 if keep
                cur |= mb & km;
                rem |= buf[k] & km;
                keepw |= (1ull << q) & km;
            }
            if (((gb + 16) & 63) == 0) {     // end of 64-bit chunk c
                if (t == 0) skw[c] = keepw;
                kept += __popcll(keepw);
                keepw = 0ull;
                if (kept >= POST) {          // rest cannot change output
                    for (int w = c + 1 + t; w < NWORDS; w += 32) skw[w] = 0ull;
                    done = true;
                } else if (c + 1 < NWORDS) {
                    cur = __shfl_sync(0xffffffffu, rem, c + 1);
                }
            }
            #pragma unroll
            for (int k = 0; k < 16; k++) buf[k] = nbuf[k];
        }
        if (!done && t == 0) skw[31] = keepw;
    }
    __syncthreads();

    if (tid < 32) {
        int x = __popcll(skw[tid]);
        #pragma unroll
        for (int o = 1; o < 32; o <<= 1) {
            int y = __shfl_up_sync(0xffffffffu, x, o);
            if (tid >= o) x += y;
        }
        woff[tid + 1] = x;
        if (tid == 0) woff[0] = 0;
    }
    __syncthreads();

    int total = woff[NWORDS];
    if (total > POST) total = POST;

    float* rois = out;
    float* probs = out + (size_t)BATCH * POST * 5;

    for (int i = tid; i < PRE; i += blockDim.x) {
        unsigned long long w = skw[i >> 6];
        if ((w >> (i & 63)) & 1ull) {
            int s = woff[i >> 6] + __popcll(w & ((1ull << (i & 63)) - 1ull));
            if (s < POST) {
                float4 b = g_box[img][i];
                size_t row = (size_t)(img * POST + s) * 5;
                rois[row + 0] = (float)img;
                rois[row + 1] = b.x;
                rois[row + 2] = b.y;
                rois[row + 3] = b.z;
                rois[row + 4] = b.w;
                probs[img * POST + s] = g_tsc[img][i];
            }
        }
    }
    for (int s = total + tid; s < POST; s += blockDim.x) {
        size_t row = (size_t)(img * POST + s) * 5;
        rois[row + 0] = (float)img;
        rois[row + 1] = 0.0f;
        rois[row + 2] = 0.0f;
        rois[row + 3] = 0.0f;
        rois[row + 4] = 0.0f;
        probs[img * POST + s] = 0.0f;
    }
}

// ---------------- launch ----------------
extern "C" void kernel_launch(void* const* d_in, const int* in_sizes, int n_in,
                              void* d_out, int out_size) {
    const float* cls     = (const float*)d_in[0];
    const float* pred    = (const float*)d_in[1];
    const float* iminfo  = (const float*)d_in[2];
    const float* anchors = (const float*)d_in[3];
    float* out = (float*)d_out;

    k_topk<<<dim3(TBX, BATCH), 256>>>(cls);
    k_sort<<<BATCH, 1024>>>();
    k_props<<<dim3(8, BATCH), 256>>>(pred, iminfo, anchors);
    k_nmsmask<<<dim3(NWORDS, (PRE + ROWT - 1) / ROWT, BATCH), 64>>>();
    k_reduce_out<<<BATCH, 256>>>(out);
}

// round 16
// speedup vs baseline: 1.1037x; 1.0984x over previous
#include <cuda_runtime.h>
#include <math.h>
#include <stdint.h>

#define BATCH 8
#define ANUM 15
#define HH 100
#define WW 168
#define NPER (ANUM*HH*WW)      // 252000
#define N4 (NPER/4)            // 63000
#define PRE 2000
#define POST 1000
#define CAND_CAP 4096
#define NWORDS 32              // ceil(PRE/64)
#define ROWT 256               // rows per nms tile
#define STRIDEF 8.0f
#define TBX 64                 // blocks per image in k_topk
#define TOPK_NB (TBX*BATCH)    // 512 blocks total (<= 4/SM * 148 = 592)

// ---------------- scratch (no allocations allowed) ----------------
__device__ unsigned int       g_hist0[BATCH][256];   // zeroed by k_reduce_out
__device__ unsigned int       g_hist1[BATCH][256];
__device__ unsigned long long g_cand[BATCH][CAND_CAP];
__device__ int                g_ccnt[BATCH];         // read+reset by tid0 of k_sort
__device__ float              g_tsc[BATCH][PRE];
__device__ int                g_ridx[BATCH][PRE];    // sorted anchor indices
__device__ float4             g_box[BATCH][PRE];     // (x1,y1,x2,y2) output
__device__ float4             g_boxn[BATCH][PRE];    // (-x1,-y1,x2,y2) for IoU
__device__ float              g_area[BATCH][PRE];    // exact reference-order area
__device__ float              g_a07[BATCH][PRE];     // 0.7f * area
__device__ unsigned int       g_valmask32[BATCH][64];
__device__ unsigned long long g_mask[BATCH][PRE][NWORDS];   // 4 MB
__device__ unsigned int       g_barcnt;
__device__ unsigned int       g_bargen;   // monotonic across replays

// ---------------- grid barrier (all TOPK_NB blocks co-resident) ----------
__device__ __forceinline__ void grid_barrier(unsigned int base, unsigned int k) {
    __syncthreads();
    if (threadIdx.x == 0) {
        __threadfence();
        unsigned int old = atomicAdd(&g_barcnt, 1u);
        if (old == TOPK_NB - 1u) {
            atomicExch(&g_barcnt, 0u);
            __threadfence();
            atomicAdd(&g_bargen, 1u);
        } else {
            unsigned int cur;
            do {
                __nanosleep(64);
                asm volatile("ld.acquire.gpu.u32 %0, [%1];"
                             : "=r"(cur) : "l"(&g_bargen) : "memory");
            } while ((int)(cur - (base + k)) < 0);
        }
    }
    __syncthreads();
}

__device__ __forceinline__ void suffix_scan256(unsigned int* cnts, int t) {
    #pragma unroll
    for (int off = 1; off < 256; off <<= 1) {
        unsigned int add = (t + off < 256) ? cnts[t + off] : 0u;
        __syncthreads();
        cnts[t] += add;
        __syncthreads();
    }
}

// warp-aggregated histogram add: one atomic per distinct bin per warp step
__device__ __forceinline__ void hadd(unsigned int* sh, unsigned int bin) {
    unsigned int am = __activemask();
    unsigned int m = __match_any_sync(am, bin);
    int leader = __ffs(m) - 1;
    if ((int)(threadIdx.x & 31) == leader) atomicAdd(&sh[bin], __popc(m));
}

// bitonic compare-exchange via warp shuffle (stride j <= 16)
__device__ __forceinline__ unsigned long long bshfl(
    unsigned long long v, int i, int j, int k) {
    unsigned long long p = __shfl_xor_sync(0xffffffffu, v, j);
    bool lower = (i & j) == 0;
    bool desc  = (i & k) == 0;
    bool keep_max = (lower == desc);
    bool pgreater = (p > v);
    return (keep_max == pgreater) ? p : v;
}

// ----- fused top-k: registers hold the slice; 2 grid barriers, 0 re-reads --
__global__ void __launch_bounds__(256, 4) k_topk(const float* __restrict__ cls) {
    int img = blockIdx.y;
    int blk = blockIdx.x;                  // 0..TBX-1
    int tid = threadIdx.x;
    __shared__ unsigned int sh[256];
    __shared__ unsigned int cnts[256];
    __shared__ unsigned int s_base, s_pref, s_krem, s_T;

    if (tid == 0) s_base = *(volatile unsigned int*)&g_bargen;
    sh[tid] = 0u;
    __syncthreads();
    unsigned int base = s_base;

    const uint4* p4 = (const uint4*)(cls + (size_t)img * NPER);
    uint4 val[4];
    bool  ok[4];
    #pragma unroll
    for (int c = 0; c < 4; c++) {
        int i = blk * 256 + tid + c * (TBX * 256);
        ok[c] = (i < N4);
        val[c] = ok[c] ? p4[i] : make_uint4(0u, 0u, 0u, 0u);
    }

    #pragma unroll
    for (int c = 0; c < 4; c++) {
        if (ok[c]) {
            hadd(sh, val[c].x >> 24);
            hadd(sh, val[c].y >> 24);
            hadd(sh, val[c].z >> 24);
            hadd(sh, val[c].w >> 24);
        }
    }
    __syncthreads();
    if (sh[tid]) atomicAdd(&g_hist0[img][tid], sh[tid]);
    grid_barrier(base, 1);

    cnts[tid] = __ldcg(&g_hist0[img][tid]);
    sh[tid] = 0u;
    __syncthreads();
    suffix_scan256(cnts, tid);
    {
        unsigned int St = cnts[tid];
        unsigned int Sn = (tid == 255) ? 0u : cnts[tid + 1];
        if (St >= (unsigned int)PRE && Sn < (unsigned int)PRE) {
            s_pref = (unsigned int)tid;
            s_krem = (unsigned int)PRE - Sn;
        }
    }
    __syncthreads();
    unsigned int pref = s_pref;
    unsigned int krem = s_krem;

    #pragma unroll
    for (int c = 0; c < 4; c++) {
        if (ok[c]) {
            if ((val[c].x >> 24) == pref) atomicAdd(&sh[(val[c].x >> 16) & 0xFFu], 1u);
            if ((val[c].y >> 24) == pref) atomicAdd(&sh[(val[c].y >> 16) & 0xFFu], 1u);
            if ((val[c].z >> 24) == pref) atomicAdd(&sh[(val[c].z >> 16) & 0xFFu], 1u);
            if ((val[c].w >> 24) == pref) atomicAdd(&sh[(val[c].w >> 16) & 0xFFu], 1u);
        }
    }
    __syncthreads();
    if (sh[tid]) atomicAdd(&g_hist1[img][tid], sh[tid]);
    grid_barrier(base, 2);

    cnts[tid] = __ldcg(&g_hist1[img][tid]);
    __syncthreads();
    suffix_scan256(cnts, tid);
    {
        unsigned int St = cnts[tid];
        unsigned int Sn = (tid == 255) ? 0u : cnts[tid + 1];
        if (St >= krem && Sn < krem)
            s_T = ((pref << 8) | (unsigned int)tid) << 16;
    }
    __syncthreads();
    unsigned int T = s_T;

    #pragma unroll
    for (int c = 0; c < 4; c++) {
        if (!ok[c]) continue;
        int ib = (blk * 256 + tid + c * (TBX * 256)) * 4;
        unsigned int b[4] = {val[c].x, val[c].y, val[c].z, val[c].w};
        #pragma unroll
        for (int u = 0; u < 4; u++) {
            if (b[u] >= T) {
                int idx = ib + u;
                int a = idx / (HH * WW);
                int rem = idx - a * (HH * WW);      // h*W + w
                int r = rem * ANUM + a;              // flattened (h,w,a)
                int pos = atomicAdd(&g_ccnt[img], 1);
                if (pos < CAND_CAP)
                    g_cand[img][pos] =
                        ((unsigned long long)b[u] << 32) | (unsigned int)(~r);
            }
        }
    }
}

// ------- 24-bit trim + hybrid shfl/smem bitonic sort (no props) -----------
__global__ void k_sort() {
    int img = blockIdx.x;
    int tid = threadIdx.x;                 // 1024 threads
    __shared__ unsigned long long s[CAND_CAP];
    __shared__ unsigned int h24[256];
    __shared__ int s_cnt;
    __shared__ unsigned int s_min16, s_above, s_v24, s_tot, s_idx;

    if (tid == 0) {
        s_cnt = g_ccnt[img];
        g_ccnt[img] = 0;                   // reset for next replay (single thread)
        s_min16 = 0xffffffffu;
        s_above = 0u;
        s_v24 = 0u;
        s_tot = 0x7fffffffu;
        s_idx = 0u;
    }
    if (tid < 256) h24[tid] = 0u;
    __syncthreads();
    int cnt = s_cnt;
    if (cnt > CAND_CAP) cnt = CAND_CAP;

    unsigned long long key[4];
    #pragma unroll
    for (int k = 0; k < 4; k++) {
        int i = tid + k * 1024;
        key[k] = (i < cnt) ? g_cand[img][i] : 0ull;
    }

    unsigned int m16 = 0xffffffffu;
    #pragma unroll
    for (int k = 0; k < 4; k++) {
        int i = tid + k * 1024;
        if (i < cnt) {
            unsigned int p = (unsigned int)(key[k] >> 48);
            if (p < m16) m16 = p;
        }
    }
    atomicMin(&s_min16, m16);
    __syncthreads();
    unsigned int min16 = s_min16;

    #pragma unroll
    for (int k = 0; k < 4; k++) {
        int i = tid + k * 1024;
        if (i < cnt) {
            unsigned int p = (unsigned int)(key[k] >> 48);
            if (p == min16) atomicAdd(&h24[(unsigned int)(key[k] >> 40) & 0xFFu], 1u);
            else            atomicAdd(&s_above, 1u);
        }
    }
    __syncthreads();
    #pragma unroll
    for (int off = 1; off < 256; off <<= 1) {
        unsigned int add = (tid < 256 && tid + off < 256) ? h24[tid + off] : 0u;
        __syncthreads();
        if (tid < 256) h24[tid] += add;
        __syncthreads();
    }
    if (tid < 256) {
        int krem2 = PRE - (int)s_above;
        unsigned int St = h24[tid];
        unsigned int Sn = (tid == 255) ? 0u : h24[tid + 1];
        if (krem2 > 0 && St >= (unsigned int)krem2 && Sn < (unsigned int)krem2) {
            s_v24 = (unsigned int)tid;
            s_tot = s_above + St;
        }
    }
    __syncthreads();

    if (s_tot <= 2048u) {
        unsigned int v24 = s_v24;
        for (int i = tid; i < 2048; i += 1024) s[i] = 0ull;
        __syncthreads();
        #pragma unroll
        for (int k = 0; k < 4; k++) {
            int i = tid + k * 1024;
            if (i < cnt) {
                unsigned int p = (unsigned int)(key[k] >> 48);
                bool keep = (p > min16) ||
                            (((unsigned int)(key[k] >> 40) & 0xFFu) >= v24);
                if (keep) s[atomicAdd(&s_idx, 1u)] = key[k];
            }
        }
        __syncthreads();

        int i0 = tid;
        int i1 = tid + 1024;
        unsigned long long v0 = s[i0];
        unsigned long long v1 = s[i1];

        #pragma unroll
        for (int k = 2; k <= 32; k <<= 1) {
            #pragma unroll
            for (int j = k >> 1; j >= 1; j >>= 1) {
                v0 = bshfl(v0, i0, j, k);
                v1 = bshfl(v1, i1, j, k);
            }
        }
        #pragma unroll
        for (int k = 64; k <= 2048; k <<= 1) {
            s[i0] = v0;
            s[i1] = v1;
            __syncthreads();
            for (int j = k >> 1; j >= 32; j >>= 1) {
                int i = ((tid & ~(j - 1)) << 1) | (tid & (j - 1));
                int ixj = i | j;
                unsigned long long a = s[i], b = s[ixj];
                bool descSeg = ((i & k) == 0);
                if (descSeg ? (a < b) : (a > b)) { s[i] = b; s[ixj] = a; }
                __syncthreads();
            }
            v0 = s[i0];
            v1 = s[i1];
            #pragma unroll
            for (int j = 16; j >= 1; j >>= 1) {
                v0 = bshfl(v0, i0, j, k);
                v1 = bshfl(v1, i1, j, k);
            }
        }
        s[i0] = v0;
        s[i1] = v1;
        __syncthreads();
    } else {
        // fallback: full-smem bitonic (rare)
        #pragma unroll
        for (int k = 0; k < 4; k++) s[tid + k * 1024] = key[k];
        int n = (cnt <= 2048) ? 2048 : 4096;
        __syncthreads();
        for (int k = 2; k <= n; k <<= 1) {
            for (int j = k >> 1; j > 0; j >>= 1) {
                for (int i = tid; i < n; i += 1024) {
                    int ixj = i ^ j;
                    if (ixj > i) {
                        unsigned long long a = s[i], b = s[ixj];
                        bool descSeg = ((i & k) == 0);
                        if (descSeg ? (a < b) : (a > b)) { s[i] = b; s[ixj] = a; }
                    }
                }
                __syncthreads();
            }
        }
    }

    #pragma unroll
    for (int pass = 0; pass < 2; pass++) {
        int i = tid + pass * 1024;
        if (i < PRE) {
            unsigned long long kk = s[i];
            g_tsc[img][i] = __uint_as_float((unsigned int)(kk >> 32));
            g_ridx[img][i] = (int)(~(unsigned int)kk);
        }
    }
}

// ------- bbox transform + clip + validity (wide grid: FP64 spread) --------
__global__ void __launch_bounds__(256) k_props(const float* __restrict__ pred,
                                               const float* __restrict__ iminfo,
                                               const float* __restrict__ anchors) {
    int img = blockIdx.y;
    int i = blockIdx.x * 256 + threadIdx.x;    // < 2048
    bool valid = false;
    float x1 = 0.f, y1 = 0.f, x2 = 0.f, y2 = 0.f, area = 0.f;

    if (i < PRE) {
        int r = g_ridx[img][i];
        int a = r % ANUM;
        int t2 = r / ANUM;
        int w = t2 % WW;
        int h = t2 / WW;

        float sx = (float)w * STRIDEF;
        float sy = (float)h * STRIDEF;
        float ax1 = __fadd_rn(anchors[a * 4 + 0], sx);
        float ay1 = __fadd_rn(anchors[a * 4 + 1], sy);
        float ax2 = __fadd_rn(anchors[a * 4 + 2], sx);
        float ay2 = __fadd_rn(anchors[a * 4 + 3], sy);

        float ws = __fadd_rn(__fsub_rn(ax2, ax1), 1.0f);
        float hs = __fadd_rn(__fsub_rn(ay2, ay1), 1.0f);
        float cx = __fadd_rn(ax1, __fmul_rn(0.5f, ws));
        float cy = __fadd_rn(ay1, __fmul_rn(0.5f, hs));

        size_t bidx = (((size_t)img * (4 * ANUM) + 4 * a) * HH + h) * WW + w;
        float dx = pred[bidx];
        float dy = pred[bidx + (size_t)HH * WW];
        float dw = pred[bidx + 2 * (size_t)HH * WW];
        float dh = pred[bidx + 3 * (size_t)HH * WW];
        const float XCLIP = 4.135166556742356f; // log(1000/16)
        dw = fminf(dw, XCLIP);
        dh = fminf(dh, XCLIP);

        float pcx = __fadd_rn(__fmul_rn(dx, ws), cx);
        float pcy = __fadd_rn(__fmul_rn(dy, hs), cy);
        float ew = (float)exp((double)dw);     // double exp -> correctly rounded f32
        float eh = (float)exp((double)dh);
        float pw = __fmul_rn(ew, ws);
        float ph = __fmul_rn(eh, hs);

        x1 = __fsub_rn(pcx, __fmul_rn(0.5f, pw));
        y1 = __fsub_rn(pcy, __fmul_rn(0.5f, ph));
        x2 = __fsub_rn(__fadd_rn(pcx, __fmul_rn(0.5f, pw)), 1.0f);
        y2 = __fsub_rn(__fadd_rn(pcy, __fmul_rn(0.5f, ph)), 1.0f);

        float im_h = iminfo[img * 3 + 0];
        float im_w = iminfo[img * 3 + 1];
        float scale = iminfo[img * 3 + 2];
        float wmax = __fsub_rn(im_w, 1.0f);
        float hmax = __fsub_rn(im_h, 1.0f);
        x1 = fminf(fmaxf(x1, 0.0f), wmax);
        y1 = fminf(fmaxf(y1, 0.0f), hmax);
        x2 = fminf(fmaxf(x2, 0.0f), wmax);
        y2 = fminf(fmaxf(y2, 0.0f), hmax);

        float ws2 = __fadd_rn(__fsub_rn(x2, x1), 1.0f);
        float hs2 = __fadd_rn(__fsub_rn(y2, y1), 1.0f);
        float ms = __fmul_rn(0.0f, scale);     // MIN_SIZE = 0
        valid = (ws2 >= ms) & (hs2 >= ms)
              & (__fadd_rn(x1, __fmul_rn(ws2, 0.5f)) < im_w)
              & (__fadd_rn(y1, __fmul_rn(hs2, 0.5f)) < im_h);
        area = __fmul_rn(ws2, hs2);
    }

    unsigned int bm = __ballot_sync(0xffffffffu, valid);
    if ((threadIdx.x & 31) == 0) g_valmask32[img][i >> 5] = bm;
    if (i < PRE) {
        g_box[img][i]  = make_float4(x1, y1, x2, y2);
        g_boxn[img][i] = make_float4(-x1, -y1, x2, y2);
        g_area[img][i] = area;
        g_a07[img][i]  = __fmul_rn(0.7f, area);
    }
}

// ----- NMS bitmask: 128 thr / 2 rows, 32-bit accumulators, exact fixup -----
__global__ void __launch_bounds__(128) k_nmsmask() {
    int img = blockIdx.z;
    int rt = blockIdx.y;
    int cb = blockIdx.x;
    int t = threadIdx.x;                 // 0..127
    int j0 = cb * 64;
    int rbase = rt * ROWT;

    if (j0 + 64 <= rbase) {
        #pragma unroll
        for (int r = 0; r < 2; r++) {
            int i = rbase + r * 128 + t;
            if (i < PRE) g_mask[img][i][cb] = 0ull;
        }
        return;
    }

    __shared__ float4 cb4[64];
    __shared__ float  ca[64];
    __shared__ float  c07[64];
    if (t < 64) {
        int j = j0 + t;
        if (j < PRE) {
            cb4[t] = g_boxn[img][j];
            ca[t]  = g_area[img][j];
            c07[t] = g_a07[img][j];
        } else {
            cb4[t] = make_float4(-1e30f, -1e30f, -1e30f, -1e30f);
            ca[t]  = 1.0f;
            c07[t] = 0.7f;
        }
    }
    __syncthreads();

    float4 rb[2];
    float  ra[2], r07[2];
    int    ri[2];
    #pragma unroll
    for (int r = 0; r < 2; r++) {
        ri[r] = rbase + r * 128 + t;
        if (ri[r] < PRE) {
            rb[r]  = g_boxn[img][ri[r]];
            ra[r]  = g_area[img][ri[r]];
            r07[r] = g_a07[img][ri[r]];
        } else {
            rb[r]  = make_float4(-1e30f, -1e30f, -1e30f, -1e30f);
            ra[r]  = 1.0f;
            r07[r] = 0.7f;
        }
    }

    const float INF = __int_as_float(0x7f800000);
    unsigned int blo[2] = {0u, 0u}, bhi[2] = {0u, 0u};
    unsigned int rlo[2] = {0u, 0u}, rhi[2] = {0u, 0u};

    #pragma unroll 4
    for (int q = 0; q < 32; q++) {
        float4 c = cb4[q];
        float c07q = c07[q];
        unsigned int m = 1u << q;
        #pragma unroll
        for (int r = 0; r < 2; r++) {
            float iw = fmaxf(__fadd_rn(__fadd_rn(fminf(rb[r].z, c.z), fminf(rb[r].x, c.x)), 1.0f), 0.0f);
            float ih = fmaxf(__fadd_rn(__fadd_rn(fminf(rb[r].w, c.w), fminf(rb[r].y, c.y)), 1.0f), 0.0f);
            float inter = __fmul_rn(iw, ih);
            float s07 = __fadd_rn(r07[r], c07q);
            float d2 = __fmaf_rn(1.7f, inter, -s07);
            float th = (s07 > 0.0f) ? __fmul_rn(s07, 1e-5f) : INF;
            if (d2 > 0.0f) blo[r] |= m;
            if (fabsf(d2) <= th) rlo[r] |= m;
        }
    }
    #pragma unroll 4
    for (int q = 32; q < 64; q++) {
        float4 c = cb4[q];
        float c07q = c07[q];
        unsigned int m = 1u << (q - 32);
        #pragma unroll
        for (int r = 0; r < 2; r++) {
            float iw = fmaxf(__fadd_rn(__fadd_rn(fminf(rb[r].z, c.z), fminf(rb[r].x, c.x)), 1.0f), 0.0f);
            float ih = fmaxf(__fadd_rn(__fadd_rn(fminf(rb[r].w, c.w), fminf(rb[r].y, c.y)), 1.0f), 0.0f);
            float inter = __fmul_rn(iw, ih);
            float s07 = __fadd_rn(r07[r], c07q);
            float d2 = __fmaf_rn(1.7f, inter, -s07);
            float th = (s07 > 0.0f) ? __fmul_rn(s07, 1e-5f) : INF;
            if (d2 > 0.0f) bhi[r] |= m;
            if (fabsf(d2) <= th) rhi[r] |= m;
        }
    }

    // exact reference-order fixup for pairs inside the screen band (rare)
    #pragma unroll
    for (int r = 0; r < 2; r++) {
        unsigned int rr = rlo[r];
        while (rr) {
            int q = __ffs(rr) - 1;
            rr &= rr - 1u;
            float4 c = cb4[q];
            float iw = fmaxf(__fadd_rn(__fadd_rn(fminf(rb[r].z, c.z), fminf(rb[r].x, c.x)), 1.0f), 0.0f);
            float ih = fmaxf(__fadd_rn(__fadd_rn(fminf(rb[r].w, c.w), fminf(rb[r].y, c.y)), 1.0f), 0.0f);
            float inter = __fmul_rn(iw, ih);
            float denom = __fsub_rn(__fadd_rn(ra[r], ca[q]), inter);
            bool sup = (__fdiv_rn(inter, denom) > 0.7f);
            unsigned int m = 1u << q;
            if (sup) blo[r] |= m;
            else     blo[r] &= ~m;
        }
        rr = rhi[r];
        while (rr) {
            int q2 = __ffs(rr) - 1;
            rr &= rr - 1u;
            int q = q2 + 32;
            float4 c = cb4[q];
            float iw = fmaxf(__fadd_rn(__fadd_rn(fminf(rb[r].z, c.z), fminf(rb[r].x, c.x)), 1.0f), 0.0f);
            float ih = fmaxf(__fadd_rn(__fadd_rn(fminf(rb[r].w, c.w), fminf(rb[r].y, c.y)), 1.0f), 0.0f);
            float inter = __fmul_rn(iw, ih);
            float denom = __fsub_rn(__fadd_rn(ra[r], ca[q]), inter);
            bool sup = (__fdiv_rn(inter, denom) > 0.7f);
            unsigned int m = 1u << q2;
            if (sup) bhi[r] |= m;
            else     bhi[r] &= ~m;
        }
    }

    int colend = PRE - j0;
    unsigned long long colmask = (colend >= 64) ? ~0ull : ((1ull << colend) - 1ull);
    #pragma unroll
    for (int r = 0; r < 2; r++) {
        int i = ri[r];
        if (i < PRE) {
            unsigned long long m =
                ((((unsigned long long)bhi[r]) << 32) | (unsigned long long)blo[r]) & colmask;
            if (i >= j0) {
                int low = i - j0 + 1;
                m = (low >= 64) ? 0ull : (m & ~((1ull << low) - 1ull));
            }
            g_mask[img][i][cb] = m;
        }
    }
}

// ------- fused: branchless greedy reduce (warp 0) + early exit + output ----
__global__ void __launch_bounds__(256) k_reduce_out(float* __restrict__ out) {
    int img = blockIdx.x;
    int tid = threadIdx.x;
    __shared__ unsigned long long skw[NWORDS];
    __shared__ int woff[NWORDS + 1];

    // re-zero histograms for the next replay (after all k_topk reads)
    if (tid < 64) ((uint4*)g_hist0[img])[tid] = make_uint4(0u, 0u, 0u, 0u);
    else if (tid < 128) ((uint4*)g_hist1[img])[tid - 64] = make_uint4(0u, 0u, 0u, 0u);

    if (tid < 32) {
        int t = tid;
        unsigned int v0 = g_valmask32[img][2 * t];
        unsigned int v1 = g_valmask32[img][2 * t + 1];
        unsigned long long rem = ~(((unsigned long long)v1 << 32) | (unsigned long long)v0);

        const unsigned long long* mrow = &g_mask[img][0][t];

        unsigned long long buf[16];
        #pragma unroll
        for (int k = 0; k < 16; k++) buf[k] = mrow[k * 32];

        unsigned long long keepw = 0ull;
        unsigned long long cur = __shfl_sync(0xffffffffu, rem, 0);
        int kept = 0;
        bool done = false;

        for (int g = 0; g < 125 && !done; g++) {
            unsigned long long nbuf[16];
            if (g < 124) {
                #pragma unroll
                for (int k = 0; k < 16; k++) nbuf[k] = mrow[(g + 1) * 512 + k * 32];
            }
            int gb = g * 16;
            int c = gb >> 6;
            #pragma unroll
            for (int k = 0; k < 16; k++) {
                int q = (gb + k) & 63;
                unsigned long long mb = __shfl_sync(0xffffffffu, buf[k], c);
                unsigned long long bitv = (cur >> q) & 1ull;     // 1 = suppressed
                unsigned long long km = bitv - 1ull;             // ~0 if keep
                cur |= mb & km;
                rem |= buf[k] & km;
                keepw |= (1ull << q) & km;
            }
            if (((gb + 16) & 63) == 0) {     // end of 64-bit chunk c
                if (t == 0) skw[c] = keepw;
                kept += __popcll(keepw);
                keepw = 0ull;
                if (kept >= POST) {          // rest cannot change output
                    for (int w = c + 1 + t; w < NWORDS; w += 32) skw[w] = 0ull;
                    done = true;
                } else if (c + 1 < NWORDS) {
                    cur = __shfl_sync(0xffffffffu, rem, c + 1);
                }
            }
            #pragma unroll
            for (int k = 0; k < 16; k++) buf[k] = nbuf[k];
        }
        if (!done && t == 0) skw[31] = keepw;
    }
    __syncthreads();

    if (tid < 32) {
        int x = __popcll(skw[tid]);
        #pragma unroll
        for (int o = 1; o < 32; o <<= 1) {
            int y = __shfl_up_sync(0xffffffffu, x, o);
            if (tid >= o) x += y;
        }
        woff[tid + 1] = x;
        if (tid == 0) woff[0] = 0;
    }
    __syncthreads();

    int total = woff[NWORDS];
    if (total > POST) total = POST;

    float* rois = out;
    float* probs = out + (size_t)BATCH * POST * 5;

    for (int i = tid; i < PRE; i += blockDim.x) {
        unsigned long long w = skw[i >> 6];
        if ((w >> (i & 63)) & 1ull) {
            int s = woff[i >> 6] + __popcll(w & ((1ull << (i & 63)) - 1ull));
            if (s < POST) {
                float4 b = g_box[img][i];
                size_t row = (size_t)(img * POST + s) * 5;
                rois[row + 0] = (float)img;
                rois[row + 1] = b.x;
                rois[row + 2] = b.y;
                rois[row + 3] = b.z;
                rois[row + 4] = b.w;
                probs[img * POST + s] = g_tsc[img][i];
            }
        }
    }
    for (int s = total + tid; s < POST; s += blockDim.x) {
        size_t row = (size_t)(img * POST + s) * 5;
        rois[row + 0] = (float)img;
        rois[row + 1] = 0.0f;
        rois[row + 2] = 0.0f;
        rois[row + 3] = 0.0f;
        rois[row + 4] = 0.0f;
        probs[img * POST + s] = 0.0f;
    }
}

// ---------------- launch ----------------
extern "C" void kernel_launch(void* const* d_in, const int* in_sizes, int n_in,
                              void* d_out, int out_size) {
    const float* cls     = (const float*)d_in[0];
    const float* pred    = (const float*)d_in[1];
    const float* iminfo  = (const float*)d_in[2];
    const float* anchors = (const float*)d_in[3];
    float* out = (float*)d_out;

    k_topk<<<dim3(TBX, BATCH), 256>>>(cls);
    k_sort<<<BATCH, 1024>>>();
    k_props<<<dim3(8, BATCH), 256>>>(pred, iminfo, anchors);
    k_nmsmask<<<dim3(NWORDS, (PRE + ROWT - 1) / ROWT, BATCH), 128>>>();
    k_reduce_out<<<BATCH, 256>>>(out);
}